// round 14
// baseline (speedup 1.0000x reference)
#include <cuda_runtime.h>
#include <cuda_fp16.h>
#include <cstdint>
#include <cstddef>

#define B_   64
#define T_   512
#define D_   1024
#define H_   1024
#define G3_  3072
#define MTOT (B_ * T_)   // 32768

// ---------------- scratch (device globals: no allocation allowed) ----------
__device__ float    g_GI[(size_t)T_ * B_ * G3_];   // [T][B][3H]
__device__ __half   g_Xh[(size_t)MTOT * D_];       // X fp16, k-permuted
__device__ __half   g_Wh[(size_t)G3_ * D_];        // W_ih fp16, k-permuted
__device__ __half   g_hp[2][B_ * H_];              // hidden fp16 ping-pong
__device__ unsigned g_qcnt[4];                     // per-k-quarter write counters
__device__ unsigned g_rdcnt;                       // staging-complete counter

// ---------------- helpers --------------------------------------------------
__device__ __forceinline__ void mma_f16(float c[4], const unsigned a[4],
                                        const unsigned b[2]) {
  asm volatile(
      "mma.sync.aligned.m16n8k16.row.col.f32.f16.f16.f32 "
      "{%0,%1,%2,%3},{%4,%5,%6,%7},{%8,%9},{%0,%1,%2,%3};\n"
      : "+f"(c[0]), "+f"(c[1]), "+f"(c[2]), "+f"(c[3])
      : "r"(a[0]), "r"(a[1]), "r"(a[2]), "r"(a[3]), "r"(b[0]), "r"(b[1]));
}

__device__ __forceinline__ uint32_t smem_u32(const void* p) {
  uint32_t a;
  asm("{ .reg .u64 t; cvta.to.shared.u64 t, %1; cvt.u32.u64 %0, t; }"
      : "=r"(a) : "l"(p));
  return a;
}

__device__ __forceinline__ void cp16(uint32_t dst, const void* src) {
  asm volatile("cp.async.cg.shared.global [%0], [%1], 16;"
               :: "r"(dst), "l"(src) : "memory");
}
#define CP_COMMIT() asm volatile("cp.async.commit_group;" ::: "memory")
template <int N>
__device__ __forceinline__ void cp_wait() {
  asm volatile("cp.async.wait_group %0;" :: "n"(N) : "memory");
}
#define CP_WAIT(n)  asm volatile("cp.async.wait_group %0;" :: "n"(n) : "memory")

__device__ __forceinline__ unsigned ldacq(const unsigned* p) {
  unsigned v;
  asm volatile("ld.acquire.gpu.global.u32 %0, [%1];" : "=r"(v) : "l"(p) : "memory");
  return v;
}

// release-ordered add: folds the membar into the atomic (prior stores are
// visible to any thread that acquires this location's new value)
__device__ __forceinline__ void red_release_add(unsigned* p, unsigned v) {
  asm volatile("red.release.gpu.global.add.u32 [%0], %1;"
               :: "l"(p), "r"(v) : "memory");
}

// k-permutation within each 16-group (so m16n8k16 frags are single LDS.64):
// out pairs: (0,1),(8,9),(2,3),(10,11),(4,5),(12,13),(6,7),(14,15)
__device__ __forceinline__ void perm16_store(__half* dst, const float* in16) {
  __half2 o[8];
  o[0] = __floats2half2_rn(in16[0],  in16[1]);
  o[1] = __floats2half2_rn(in16[8],  in16[9]);
  o[2] = __floats2half2_rn(in16[2],  in16[3]);
  o[3] = __floats2half2_rn(in16[10], in16[11]);
  o[4] = __floats2half2_rn(in16[4],  in16[5]);
  o[5] = __floats2half2_rn(in16[12], in16[13]);
  o[6] = __floats2half2_rn(in16[6],  in16[7]);
  o[7] = __floats2half2_rn(in16[14], in16[15]);
  *(uint4*)dst       = *(const uint4*)&o[0];
  *(uint4*)(dst + 8) = *(const uint4*)&o[4];
}

// forward permuted position of k-index r within its 16-group
__device__ __forceinline__ int permpos(int r) {
  return (r < 8) ? ((r & 1) ? 2 * r - 1 : 2 * r)
                 : ((r & 1) ? 2 * r - 15 : 2 * r - 14);
}

// ============================================================================
// Phase 0: prep — fp16-convert + k-permute X, W_ih, h0.  Also resets the
// phase-2 flag counters (stream-ordered before gru on every graph replay).
// ============================================================================
__global__ void __launch_bounds__(256) prep_kernel(const float* __restrict__ X,
                                                   const float* __restrict__ W,
                                                   const float* __restrict__ h0) {
  if (blockIdx.x == 0 && threadIdx.x == 0) {
    g_qcnt[0] = 0; g_qcnt[1] = 0; g_qcnt[2] = 0; g_qcnt[3] = 0;
    g_rdcnt = 0;
  }
  const size_t nX = (size_t)MTOT * D_ / 16;
  const size_t nW = (size_t)G3_ * D_ / 16;
  const size_t nH = (size_t)B_ * H_ / 16;
  size_t stride = (size_t)gridDim.x * blockDim.x;
  for (size_t gi = (size_t)blockIdx.x * blockDim.x + threadIdx.x;
       gi < nX + nW + nH; gi += stride) {
    const float* src;
    __half* dst;
    if (gi < nX)           { src = X  + gi * 16;        dst = g_Xh + gi * 16; }
    else if (gi < nX + nW) { size_t j = gi - nX;        src = W  + j * 16; dst = g_Wh + j * 16; }
    else                   { size_t j = gi - nX - nW;   src = h0 + j * 16; dst = g_hp[0] + j * 16; }
    float in16[16];
#pragma unroll
    for (int q = 0; q < 4; q++)
      *(float4*)(in16 + 4 * q) = *(const float4*)(src + 4 * q);
    perm16_store(dst, in16);
  }
}

// ============================================================================
// Phase 1: GI = X @ W_ih^T + b_ih.  fp16 m16n8k16 mma.sync.
// CTA 128x128, 4 warps (warp tile 64x64), K-chunk 64, cp.async double buffer.
// 2 CTAs/SM.  (unchanged — measured at its issue floor)
// ============================================================================
#define P1S_H      80                    // halfs per smem row (64 data + 16 pad)
#define P1_STAGE_B (256 * 160)           // bytes per stage (256 rows x 160 B)
#define P1_SMEM_BYTES (2 * P1_STAGE_B)   // 81920 B

__global__ void __launch_bounds__(128) gi_gemm_kernel(const float* __restrict__ bih) {
  extern __shared__ __half smh[];
  const uint32_t sbase = smem_u32(smh);

  const int tid  = threadIdx.x;
  const int lane = tid & 31;
  const int w    = tid >> 5;
  const int wm   = w >> 1;
  const int wn   = w & 1;
  const int g    = lane >> 2;
  const int tg   = lane & 3;
  const int n0   = blockIdx.x * 128;
  const int m0   = blockIdx.y * 128;

  float acc[4][8][4];
#pragma unroll
  for (int i = 0; i < 4; i++)
#pragma unroll
    for (int j = 0; j < 8; j++)
#pragma unroll
      for (int k = 0; k < 4; k++) acc[i][j][k] = 0.f;

#define P1_ISSUE(c)                                                           \
  do {                                                                        \
    const int kc_ = (c) * 64;                                                 \
    const uint32_t db_ = sbase + ((c) & 1) * P1_STAGE_B;                      \
    _Pragma("unroll")                                                         \
    for (int i_ = 0; i_ < 16; i_++) {                                         \
      int idx_ = i_ * 128 + tid;                                              \
      int row_ = idx_ >> 3, q_ = idx_ & 7;                                    \
      const __half* src_ = (row_ < 128)                                       \
          ? g_Xh + (size_t)(m0 + row_) * D_ + kc_ + q_ * 8                    \
          : g_Wh + (size_t)(n0 + row_ - 128) * D_ + kc_ + q_ * 8;             \
      cp16(db_ + (uint32_t)(row_ * 160 + q_ * 16), src_);                     \
    }                                                                         \
    CP_COMMIT();                                                              \
  } while (0)

  P1_ISSUE(0);

  for (int c = 0; c < 16; c++) {
    if (c < 15) { P1_ISSUE(c + 1); CP_WAIT(1); }
    else        { CP_WAIT(0); }
    __syncthreads();

    const __half* As = smh + (size_t)(c & 1) * (P1_STAGE_B / 2);
    const __half* Bs = As + 128 * P1S_H;
#pragma unroll
    for (int ks = 0; ks < 4; ks++) {
      unsigned a[4][4], b[8][2];
#pragma unroll
      for (int mt = 0; mt < 4; mt++) {
        int row = wm * 64 + mt * 16 + g;
        uint2 lo = *(const uint2*)(As + (size_t)row * P1S_H + ks * 16 + 4 * tg);
        uint2 hi = *(const uint2*)(As + (size_t)(row + 8) * P1S_H + ks * 16 + 4 * tg);
        a[mt][0] = lo.x; a[mt][1] = hi.x; a[mt][2] = lo.y; a[mt][3] = hi.y;
      }
#pragma unroll
      for (int nt = 0; nt < 8; nt++) {
        int col = wn * 64 + nt * 8 + g;
        uint2 bv = *(const uint2*)(Bs + (size_t)col * P1S_H + ks * 16 + 4 * tg);
        b[nt][0] = bv.x; b[nt][1] = bv.y;
      }
#pragma unroll
      for (int mt = 0; mt < 4; mt++)
#pragma unroll
        for (int nt = 0; nt < 8; nt++) mma_f16(acc[mt][nt], a[mt], b[nt]);
    }
    __syncthreads();
  }

  // ---- epilogue: acc -> GI (+ bias) ----
#pragma unroll
  for (int mt = 0; mt < 4; mt++) {
#pragma unroll
    for (int half = 0; half < 2; half++) {
      int mrow = m0 + wm * 64 + mt * 16 + g + half * 8;
      int bb = mrow >> 9;
      int tt = mrow & (T_ - 1);
      float* go = g_GI + ((size_t)tt * B_ + bb) * G3_;
#pragma unroll
      for (int nt = 0; nt < 8; nt++) {
        int col = n0 + wn * 64 + nt * 8 + 2 * tg;
        float2 bias = *(const float2*)(bih + col);
        float2 o;
        o.x = acc[mt][nt][half * 2 + 0] + bias.x;
        o.y = acc[mt][nt][half * 2 + 1] + bias.y;
        *(float2*)(go + col) = o;
      }
    }
  }
}

// ============================================================================
// Phase 2: persistent recurrence, fp16 m16n8k16. 128 CTAs x 128 threads.
// R12 skeleton (2-deep ring, k-quarter flags, elastic staging) with:
//  - release-atomic publish (folds __threadfence into the flag atomic)
//  - vectorized epilogue stores (float2 / half2)
// ============================================================================
#define NC     8
#define NG     24
#define GRID2  128
#define WS2    1040   // halfs per Ws row
#define HS2    1040   // halfs per hs row
#define SMEM2_BYTES ((NG * WS2 + 64 * HS2) * 2)   // 183040 B

// stage k-quarter q (CTA-wide: 2048 16B chunks / 128 threads)
#define STAGE_QUARTER(q)                                                      \
  do {                                                                        \
    _Pragma("unroll")                                                         \
    for (int i_ = 0; i_ < 16; i_++) {                                         \
      int u_ = i_ * 128 + tid;                                                \
      int row_ = u_ >> 5, ch_ = u_ & 31;                                      \
      cp16(hs_base + (uint32_t)(row_ * (HS2 * 2) + (q) * 512 + ch_ * 16),     \
           hc16 + (size_t)row_ * H_ + (q) * 256 + ch_ * 8);                   \
    }                                                                         \
    CP_COMMIT();                                                              \
  } while (0)

// MMA over ks in [ks0, ks0+16)
#define MMA_QUARTER(ks0)                                                      \
  do {                                                                        \
    _Pragma("unroll")                                                         \
    for (int kq_ = 0; kq_ < 16; kq_++) {                                      \
      int ks_ = (ks0) + kq_;                                                  \
      unsigned a_[4];                                                         \
      uint2 lo_ = *(const uint2*)(arow0 + ks_ * 16);                          \
      uint2 hi_ = *(const uint2*)(arow1 + ks_ * 16);                          \
      a_[0] = lo_.x; a_[1] = hi_.x; a_[2] = lo_.y; a_[3] = hi_.y;             \
      _Pragma("unroll")                                                       \
      for (int nt_ = 0; nt_ < 3; nt_++) {                                     \
        uint2 bv_ = *(const uint2*)(Ws + (size_t)(nt_ * 8 + g) * WS2 +        \
                                    ks_ * 16 + 4 * tg);                       \
        unsigned b_[2] = {bv_.x, bv_.y};                                      \
        mma_f16(acc[nt_], a_, b_);                                            \
      }                                                                       \
    }                                                                         \
  } while (0)

__global__ void __launch_bounds__(128) gru_step_kernel(
    const float* __restrict__ Whh, const float* __restrict__ bhh,
    const float* __restrict__ h0, float* __restrict__ out) {
  extern __shared__ __half smh2[];
  __half* Ws = smh2;                    // [NG][WS2]
  __half* hs = smh2 + NG * WS2;         // [64][HS2]
  const uint32_t hs_base = smem_u32(hs);

  const int tid  = threadIdx.x;
  const int lane = tid & 31;
  const int w    = tid >> 5;
  const int g    = lane >> 2;
  const int tg   = lane & 3;
  const int j0   = blockIdx.x * NC;
  const int myq  = blockIdx.x >> 5;     // k-quarter this CTA produces

  // load W_hh slice -> fp16 permuted SMEM (once)
  for (int idx = tid; idx < NG * (H_ / 16); idx += 128) {
    int rw  = idx >> 6;           // 0..23
    int grp = idx & 63;           // 16-group within row
    int row = ((rw >> 3) * H_) + j0 + (rw & 7);
    float in16[16];
#pragma unroll
    for (int q = 0; q < 4; q++)
      *(float4*)(in16 + 4 * q) = *(const float4*)(Whh + (size_t)row * H_ + grp * 16 + 4 * q);
    perm16_store(Ws + (size_t)rw * WS2 + grp * 16, in16);
  }

  float bh[3][2];
#pragma unroll
  for (int gate = 0; gate < 3; gate++) {
    bh[gate][0] = bhh[gate * H_ + j0 + 2 * tg];
    bh[gate][1] = bhh[gate * H_ + j0 + 2 * tg + 1];
  }

  // per-thread output coords; pairs (0,1) and (2,3) are column-adjacent
  int bbv[4], jv[4], jpv[4];
#pragma unroll
  for (int i = 0; i < 4; i++) {
    bbv[i] = w * 16 + g + ((i >> 1) ? 8 : 0);
    jv[i]  = j0 + 2 * tg + (i & 1);
    jpv[i] = (jv[i] & ~15) | permpos(jv[i] & 15);
  }

  // h carried in registers across steps (bit-identical to re-reading `out`)
  float hvreg[4];
#pragma unroll
  for (int i = 0; i < 4; i++)
    hvreg[i] = __ldg(h0 + (size_t)bbv[i] * H_ + jv[i]);
  __syncthreads();

  for (int t = 0; t < T_; t++) {
    const __half* hc16 = g_hp[t & 1];
    const unsigned thr_w = 32u * (unsigned)t;     // quarter-ready threshold

    // hoisted GI loads (DRAM latency overlaps the flag spins below)
    float gpre[4][3];
#pragma unroll
    for (int i = 0; i < 4; i++) {
      size_t gio = ((size_t)t * B_ + bbv[i]) * G3_ + jv[i];
      gpre[i][0] = __ldg(g_GI + gio);
      gpre[i][1] = __ldg(g_GI + gio + H_);
      gpre[i][2] = __ldg(g_GI + gio + 2 * H_);
    }

    // ---- stage quarters 0,1 as soon as their 32 producers are done ----
    if (t > 0) { while (ldacq(&g_qcnt[0]) < thr_w) { } }
    STAGE_QUARTER(0);
    if (t > 0) { while (ldacq(&g_qcnt[1]) < thr_w) { } }
    STAGE_QUARTER(1);

    float acc[3][4];
#pragma unroll
    for (int nt = 0; nt < 3; nt++) {
      acc[nt][0] = bh[nt][0]; acc[nt][1] = bh[nt][1];
      acc[nt][2] = bh[nt][0]; acc[nt][3] = bh[nt][1];
    }

    const __half* arow0 = hs + (size_t)(w * 16 + g) * HS2 + 4 * tg;
    const __half* arow1 = arow0 + 8 * HS2;

    // ---- MMA q0 (q1 in flight), then stage q2/q3 between MMA quarters ----
    cp_wait<1>(); __syncthreads();
    MMA_QUARTER(0);

    if (t > 0) { while (ldacq(&g_qcnt[2]) < thr_w) { } }
    STAGE_QUARTER(2);
    cp_wait<1>(); __syncthreads();
    MMA_QUARTER(16);

    if (t > 0) { while (ldacq(&g_qcnt[3]) < thr_w) { } }
    STAGE_QUARTER(3);
    cp_wait<1>(); __syncthreads();
    MMA_QUARTER(32);

    cp_wait<0>(); __syncthreads();
    if (tid == 0) red_release_add(&g_rdcnt, 1u);  // slot reads complete
    MMA_QUARTER(48);

    // ---- WAR guard: all CTAs must have staged step t-1 before we
    //      overwrite slot (t+1)&1 (which holds h[t-1]) ----
    if (t > 0) { while (ldacq(&g_rdcnt) < 128u * (unsigned)t) { } }

    // ---- gate math ----
    float hnew[4];
#pragma unroll
    for (int i = 0; i < 4; i++) {
      float rg = 1.f / (1.f + __expf(-(gpre[i][0] + acc[0][i])));
      float zg = 1.f / (1.f + __expf(-(gpre[i][1] + acc[1][i])));
      float nn = tanhf(gpre[i][2] + rg * acc[2][i]);
      hnew[i] = (1.f - zg) * nn + zg * hvreg[i];
      hvreg[i] = hnew[i];
    }

    // ---- vectorized stores (pairs (0,1) and (2,3) are adjacent cols) ----
    __half* hn16 = g_hp[(t + 1) & 1];
#pragma unroll
    for (int p = 0; p < 2; p++) {
      int i0 = 2 * p;
      float2 o = make_float2(hnew[i0], hnew[i0 + 1]);
      *(float2*)(out + ((size_t)bbv[i0] * T_ + t) * H_ + jv[i0]) = o;
      __half2 hp = __floats2half2_rn(hnew[i0], hnew[i0 + 1]);
      *(__half2*)(hn16 + (size_t)bbv[i0] * H_ + jpv[i0]) = hp;
      if (t == T_ - 1)
        *(float2*)(out + (size_t)B_ * T_ * H_ + (size_t)bbv[i0] * H_ + jv[i0]) = o;
    }

    // ---- publish this CTA's h columns for step t+1 (release atomic) ----
    if (t < T_ - 1) {
      __syncthreads();
      if (tid == 0) red_release_add(&g_qcnt[myq], 1u);
    }
  }
}

// ============================================================================
extern "C" void kernel_launch(void* const* d_in, const int* in_sizes, int n_in,
                              void* d_out, int out_size) {
  const float* X   = (const float*)d_in[0];
  const float* Wih = (const float*)d_in[1];
  const float* Whh = (const float*)d_in[2];
  const float* bih = (const float*)d_in[3];
  const float* bhh = (const float*)d_in[4];
  const float* h0  = (const float*)d_in[5];
  float* out = (float*)d_out;

  cudaFuncSetAttribute(gi_gemm_kernel,
                       cudaFuncAttributeMaxDynamicSharedMemorySize,
                       P1_SMEM_BYTES);
  cudaFuncSetAttribute(gru_step_kernel,
                       cudaFuncAttributeMaxDynamicSharedMemorySize,
                       SMEM2_BYTES);

  // Phase 0: fp16-convert + k-permute X, W_ih, h0 (+ reset flag counters)
  prep_kernel<<<2048, 256>>>(X, Wih, h0);

  // Phase 1: input-side GEMM (fp16 m16n8k16, cp.async pipeline, 2 CTAs/SM)
  gi_gemm_kernel<<<dim3(24, 256), 128, P1_SMEM_BYTES>>>(bih);

  // Phase 2: persistent recurrence (128 CTAs, quarter flags, release publish)
  gru_step_kernel<<<GRID2, 128, SMEM2_BYTES>>>(Whh, bhh, h0, out);
}

// round 15
// speedup vs baseline: 1.1090x; 1.1090x over previous
#include <cuda_runtime.h>
#include <cuda_fp16.h>
#include <cstdint>
#include <cstddef>

#define B_   64
#define T_   512
#define D_   1024
#define H_   1024
#define G3_  3072
#define MTOT (B_ * T_)   // 32768

// ---------------- scratch (device globals: no allocation allowed) ----------
__device__ float    g_GI[(size_t)T_ * B_ * G3_];   // [T][B][3H]
__device__ __half   g_Xh[(size_t)MTOT * D_];       // X fp16, k-permuted
__device__ __half   g_Wh[(size_t)G3_ * D_];        // W_ih fp16, k-permuted
__device__ __half   g_hp[2][B_ * H_];              // hidden fp16 ping-pong
__device__ unsigned g_qcnt[4];                     // per-k-quarter write counters
__device__ unsigned g_rdcnt;                       // staging-complete counter

// ---------------- helpers --------------------------------------------------
__device__ __forceinline__ void mma_f16(float c[4], const unsigned a[4],
                                        const unsigned b[2]) {
  asm volatile(
      "mma.sync.aligned.m16n8k16.row.col.f32.f16.f16.f32 "
      "{%0,%1,%2,%3},{%4,%5,%6,%7},{%8,%9},{%0,%1,%2,%3};\n"
      : "+f"(c[0]), "+f"(c[1]), "+f"(c[2]), "+f"(c[3])
      : "r"(a[0]), "r"(a[1]), "r"(a[2]), "r"(a[3]), "r"(b[0]), "r"(b[1]));
}

__device__ __forceinline__ uint32_t smem_u32(const void* p) {
  uint32_t a;
  asm("{ .reg .u64 t; cvta.to.shared.u64 t, %1; cvt.u32.u64 %0, t; }"
      : "=r"(a) : "l"(p));
  return a;
}

__device__ __forceinline__ void cp16(uint32_t dst, const void* src) {
  asm volatile("cp.async.cg.shared.global [%0], [%1], 16;"
               :: "r"(dst), "l"(src) : "memory");
}
#define CP_COMMIT() asm volatile("cp.async.commit_group;" ::: "memory")
template <int N>
__device__ __forceinline__ void cp_wait() {
  asm volatile("cp.async.wait_group %0;" :: "n"(N) : "memory");
}
#define CP_WAIT(n)  asm volatile("cp.async.wait_group %0;" :: "n"(n) : "memory")

__device__ __forceinline__ unsigned ldacq(const unsigned* p) {
  unsigned v;
  asm volatile("ld.acquire.gpu.global.u32 %0, [%1];" : "=r"(v) : "l"(p) : "memory");
  return v;
}

// release-ordered add: folds the membar into the atomic (prior stores are
// visible to any thread whose acquire-load observes the new value)
__device__ __forceinline__ void red_release_add(unsigned* p, unsigned v) {
  asm volatile("red.release.gpu.global.add.u32 [%0], %1;"
               :: "l"(p), "r"(v) : "memory");
}

// k-permutation within each 16-group (so m16n8k16 frags are single LDS.64):
// out pairs: (0,1),(8,9),(2,3),(10,11),(4,5),(12,13),(6,7),(14,15)
__device__ __forceinline__ void perm16_store(__half* dst, const float* in16) {
  __half2 o[8];
  o[0] = __floats2half2_rn(in16[0],  in16[1]);
  o[1] = __floats2half2_rn(in16[8],  in16[9]);
  o[2] = __floats2half2_rn(in16[2],  in16[3]);
  o[3] = __floats2half2_rn(in16[10], in16[11]);
  o[4] = __floats2half2_rn(in16[4],  in16[5]);
  o[5] = __floats2half2_rn(in16[12], in16[13]);
  o[6] = __floats2half2_rn(in16[6],  in16[7]);
  o[7] = __floats2half2_rn(in16[14], in16[15]);
  *(uint4*)dst       = *(const uint4*)&o[0];
  *(uint4*)(dst + 8) = *(const uint4*)&o[4];
}

// forward permuted position of k-index r within its 16-group
__device__ __forceinline__ int permpos(int r) {
  return (r < 8) ? ((r & 1) ? 2 * r - 1 : 2 * r)
                 : ((r & 1) ? 2 * r - 15 : 2 * r - 14);
}

// ============================================================================
// Phase 0: prep — fp16-convert + k-permute X, W_ih, h0.  Also resets the
// phase-2 flag counters (stream-ordered before gru on every graph replay).
// ============================================================================
__global__ void __launch_bounds__(256) prep_kernel(const float* __restrict__ X,
                                                   const float* __restrict__ W,
                                                   const float* __restrict__ h0) {
  if (blockIdx.x == 0 && threadIdx.x == 0) {
    g_qcnt[0] = 0; g_qcnt[1] = 0; g_qcnt[2] = 0; g_qcnt[3] = 0;
    g_rdcnt = 0;
  }
  const size_t nX = (size_t)MTOT * D_ / 16;
  const size_t nW = (size_t)G3_ * D_ / 16;
  const size_t nH = (size_t)B_ * H_ / 16;
  size_t stride = (size_t)gridDim.x * blockDim.x;
  for (size_t gi = (size_t)blockIdx.x * blockDim.x + threadIdx.x;
       gi < nX + nW + nH; gi += stride) {
    const float* src;
    __half* dst;
    if (gi < nX)           { src = X  + gi * 16;        dst = g_Xh + gi * 16; }
    else if (gi < nX + nW) { size_t j = gi - nX;        src = W  + j * 16; dst = g_Wh + j * 16; }
    else                   { size_t j = gi - nX - nW;   src = h0 + j * 16; dst = g_hp[0] + j * 16; }
    float in16[16];
#pragma unroll
    for (int q = 0; q < 4; q++)
      *(float4*)(in16 + 4 * q) = *(const float4*)(src + 4 * q);
    perm16_store(dst, in16);
  }
}

// ============================================================================
// Phase 1: GI = X @ W_ih^T + b_ih.  fp16 m16n8k16 mma.sync.
// CTA 128x128, 4 warps (warp tile 64x64), K-chunk 64, cp.async double buffer.
// 2 CTAs/SM.  (unchanged — measured at its issue floor)
// ============================================================================
#define P1S_H      80                    // halfs per smem row (64 data + 16 pad)
#define P1_STAGE_B (256 * 160)           // bytes per stage (256 rows x 160 B)
#define P1_SMEM_BYTES (2 * P1_STAGE_B)   // 81920 B

__global__ void __launch_bounds__(128) gi_gemm_kernel(const float* __restrict__ bih) {
  extern __shared__ __half smh[];
  const uint32_t sbase = smem_u32(smh);

  const int tid  = threadIdx.x;
  const int lane = tid & 31;
  const int w    = tid >> 5;
  const int wm   = w >> 1;
  const int wn   = w & 1;
  const int g    = lane >> 2;
  const int tg   = lane & 3;
  const int n0   = blockIdx.x * 128;
  const int m0   = blockIdx.y * 128;

  float acc[4][8][4];
#pragma unroll
  for (int i = 0; i < 4; i++)
#pragma unroll
    for (int j = 0; j < 8; j++)
#pragma unroll
      for (int k = 0; k < 4; k++) acc[i][j][k] = 0.f;

#define P1_ISSUE(c)                                                           \
  do {                                                                        \
    const int kc_ = (c) * 64;                                                 \
    const uint32_t db_ = sbase + ((c) & 1) * P1_STAGE_B;                      \
    _Pragma("unroll")                                                         \
    for (int i_ = 0; i_ < 16; i_++) {                                         \
      int idx_ = i_ * 128 + tid;                                              \
      int row_ = idx_ >> 3, q_ = idx_ & 7;                                    \
      const __half* src_ = (row_ < 128)                                       \
          ? g_Xh + (size_t)(m0 + row_) * D_ + kc_ + q_ * 8                    \
          : g_Wh + (size_t)(n0 + row_ - 128) * D_ + kc_ + q_ * 8;             \
      cp16(db_ + (uint32_t)(row_ * 160 + q_ * 16), src_);                     \
    }                                                                         \
    CP_COMMIT();                                                              \
  } while (0)

  P1_ISSUE(0);

  for (int c = 0; c < 16; c++) {
    if (c < 15) { P1_ISSUE(c + 1); CP_WAIT(1); }
    else        { CP_WAIT(0); }
    __syncthreads();

    const __half* As = smh + (size_t)(c & 1) * (P1_STAGE_B / 2);
    const __half* Bs = As + 128 * P1S_H;
#pragma unroll
    for (int ks = 0; ks < 4; ks++) {
      unsigned a[4][4], b[8][2];
#pragma unroll
      for (int mt = 0; mt < 4; mt++) {
        int row = wm * 64 + mt * 16 + g;
        uint2 lo = *(const uint2*)(As + (size_t)row * P1S_H + ks * 16 + 4 * tg);
        uint2 hi = *(const uint2*)(As + (size_t)(row + 8) * P1S_H + ks * 16 + 4 * tg);
        a[mt][0] = lo.x; a[mt][1] = hi.x; a[mt][2] = lo.y; a[mt][3] = hi.y;
      }
#pragma unroll
      for (int nt = 0; nt < 8; nt++) {
        int col = wn * 64 + nt * 8 + g;
        uint2 bv = *(const uint2*)(Bs + (size_t)col * P1S_H + ks * 16 + 4 * tg);
        b[nt][0] = bv.x; b[nt][1] = bv.y;
      }
#pragma unroll
      for (int mt = 0; mt < 4; mt++)
#pragma unroll
        for (int nt = 0; nt < 8; nt++) mma_f16(acc[mt][nt], a[mt], b[nt]);
    }
    __syncthreads();
  }

  // ---- epilogue: acc -> GI (+ bias) ----
#pragma unroll
  for (int mt = 0; mt < 4; mt++) {
#pragma unroll
    for (int half = 0; half < 2; half++) {
      int mrow = m0 + wm * 64 + mt * 16 + g + half * 8;
      int bb = mrow >> 9;
      int tt = mrow & (T_ - 1);
      float* go = g_GI + ((size_t)tt * B_ + bb) * G3_;
#pragma unroll
      for (int nt = 0; nt < 8; nt++) {
        int col = n0 + wn * 64 + nt * 8 + 2 * tg;
        float2 bias = *(const float2*)(bih + col);
        float2 o;
        o.x = acc[mt][nt][half * 2 + 0] + bias.x;
        o.y = acc[mt][nt][half * 2 + 1] + bias.y;
        *(float2*)(go + col) = o;
      }
    }
  }
}

// ============================================================================
// Phase 2: persistent recurrence, fp16 m16n8k16. 128 CTAs x 128 threads.
// EXACT R12 skeleton (2-deep ring, k-quarter flags, elastic staging, scalar
// epilogue stores) with ONE delta: the end-of-step publish uses a
// release-ordered atomic instead of __threadfence + plain atomic.
// ============================================================================
#define NC     8
#define NG     24
#define GRID2  128
#define WS2    1040   // halfs per Ws row
#define HS2    1040   // halfs per hs row
#define SMEM2_BYTES ((NG * WS2 + 64 * HS2) * 2)   // 183040 B

// stage k-quarter q (CTA-wide: 2048 16B chunks / 128 threads)
#define STAGE_QUARTER(q)                                                      \
  do {                                                                        \
    _Pragma("unroll")                                                         \
    for (int i_ = 0; i_ < 16; i_++) {                                         \
      int u_ = i_ * 128 + tid;                                                \
      int row_ = u_ >> 5, ch_ = u_ & 31;                                      \
      cp16(hs_base + (uint32_t)(row_ * (HS2 * 2) + (q) * 512 + ch_ * 16),     \
           hc16 + (size_t)row_ * H_ + (q) * 256 + ch_ * 8);                   \
    }                                                                         \
    CP_COMMIT();                                                              \
  } while (0)

// MMA over ks in [ks0, ks0+16)
#define MMA_QUARTER(ks0)                                                      \
  do {                                                                        \
    _Pragma("unroll")                                                         \
    for (int kq_ = 0; kq_ < 16; kq_++) {                                      \
      int ks_ = (ks0) + kq_;                                                  \
      unsigned a_[4];                                                         \
      uint2 lo_ = *(const uint2*)(arow0 + ks_ * 16);                          \
      uint2 hi_ = *(const uint2*)(arow1 + ks_ * 16);                          \
      a_[0] = lo_.x; a_[1] = hi_.x; a_[2] = lo_.y; a_[3] = hi_.y;             \
      _Pragma("unroll")                                                       \
      for (int nt_ = 0; nt_ < 3; nt_++) {                                     \
        uint2 bv_ = *(const uint2*)(Ws + (size_t)(nt_ * 8 + g) * WS2 +        \
                                    ks_ * 16 + 4 * tg);                       \
        unsigned b_[2] = {bv_.x, bv_.y};                                      \
        mma_f16(acc[nt_], a_, b_);                                            \
      }                                                                       \
    }                                                                         \
  } while (0)

__global__ void __launch_bounds__(128) gru_step_kernel(
    const float* __restrict__ Whh, const float* __restrict__ bhh,
    const float* __restrict__ h0, float* __restrict__ out) {
  extern __shared__ __half smh2[];
  __half* Ws = smh2;                    // [NG][WS2]
  __half* hs = smh2 + NG * WS2;         // [64][HS2]
  const uint32_t hs_base = smem_u32(hs);

  const int tid  = threadIdx.x;
  const int lane = tid & 31;
  const int w    = tid >> 5;
  const int g    = lane >> 2;
  const int tg   = lane & 3;
  const int j0   = blockIdx.x * NC;
  const int myq  = blockIdx.x >> 5;     // k-quarter this CTA produces

  // load W_hh slice -> fp16 permuted SMEM (once)
  for (int idx = tid; idx < NG * (H_ / 16); idx += 128) {
    int rw  = idx >> 6;           // 0..23
    int grp = idx & 63;           // 16-group within row
    int row = ((rw >> 3) * H_) + j0 + (rw & 7);
    float in16[16];
#pragma unroll
    for (int q = 0; q < 4; q++)
      *(float4*)(in16 + 4 * q) = *(const float4*)(Whh + (size_t)row * H_ + grp * 16 + 4 * q);
    perm16_store(Ws + (size_t)rw * WS2 + grp * 16, in16);
  }

  float bh[3][2];
#pragma unroll
  for (int gate = 0; gate < 3; gate++) {
    bh[gate][0] = bhh[gate * H_ + j0 + 2 * tg];
    bh[gate][1] = bhh[gate * H_ + j0 + 2 * tg + 1];
  }

  // per-thread output coords (4 accum elements)
  int bbv[4], jv[4], jpv[4];
#pragma unroll
  for (int i = 0; i < 4; i++) {
    bbv[i] = w * 16 + g + ((i >> 1) ? 8 : 0);
    jv[i]  = j0 + 2 * tg + (i & 1);
    jpv[i] = (jv[i] & ~15) | permpos(jv[i] & 15);
  }

  // h carried in registers across steps (bit-identical to re-reading `out`)
  float hvreg[4];
#pragma unroll
  for (int i = 0; i < 4; i++)
    hvreg[i] = __ldg(h0 + (size_t)bbv[i] * H_ + jv[i]);
  __syncthreads();

  for (int t = 0; t < T_; t++) {
    const __half* hc16 = g_hp[t & 1];
    const unsigned thr_w = 32u * (unsigned)t;     // quarter-ready threshold

    // hoisted GI loads (DRAM latency overlaps the flag spins below)
    float gpre[4][3];
#pragma unroll
    for (int i = 0; i < 4; i++) {
      size_t gio = ((size_t)t * B_ + bbv[i]) * G3_ + jv[i];
      gpre[i][0] = __ldg(g_GI + gio);
      gpre[i][1] = __ldg(g_GI + gio + H_);
      gpre[i][2] = __ldg(g_GI + gio + 2 * H_);
    }

    // ---- stage quarters 0,1 as soon as their 32 producers are done ----
    if (t > 0) { while (ldacq(&g_qcnt[0]) < thr_w) { } }
    STAGE_QUARTER(0);
    if (t > 0) { while (ldacq(&g_qcnt[1]) < thr_w) { } }
    STAGE_QUARTER(1);

    float acc[3][4];
#pragma unroll
    for (int nt = 0; nt < 3; nt++) {
      acc[nt][0] = bh[nt][0]; acc[nt][1] = bh[nt][1];
      acc[nt][2] = bh[nt][0]; acc[nt][3] = bh[nt][1];
    }

    const __half* arow0 = hs + (size_t)(w * 16 + g) * HS2 + 4 * tg;
    const __half* arow1 = arow0 + 8 * HS2;

    // ---- MMA q0 (q1 in flight), then stage q2/q3 between MMA quarters ----
    cp_wait<1>(); __syncthreads();
    MMA_QUARTER(0);

    if (t > 0) { while (ldacq(&g_qcnt[2]) < thr_w) { } }
    STAGE_QUARTER(2);
    cp_wait<1>(); __syncthreads();
    MMA_QUARTER(16);

    if (t > 0) { while (ldacq(&g_qcnt[3]) < thr_w) { } }
    STAGE_QUARTER(3);
    cp_wait<1>(); __syncthreads();
    MMA_QUARTER(32);

    cp_wait<0>(); __syncthreads();
    if (tid == 0) atomicAdd(&g_rdcnt, 1u);   // this CTA's slot reads complete
    MMA_QUARTER(48);

    // ---- WAR guard: all CTAs must have staged step t-1 before we
    //      overwrite slot (t+1)&1 (which holds h[t-1]) ----
    if (t > 0) { while (ldacq(&g_rdcnt) < 128u * (unsigned)t) { } }

    // ---- gate math + stores (scalar, as in R12) ----
    __half* hn16 = g_hp[(t + 1) & 1];
#pragma unroll
    for (int i = 0; i < 4; i++) {
      float rg = 1.f / (1.f + __expf(-(gpre[i][0] + acc[0][i])));
      float zg = 1.f / (1.f + __expf(-(gpre[i][1] + acc[1][i])));
      float nn = tanhf(gpre[i][2] + rg * acc[2][i]);
      float hnew = (1.f - zg) * nn + zg * hvreg[i];
      hvreg[i] = hnew;
      out[((size_t)bbv[i] * T_ + t) * H_ + jv[i]] = hnew;
      hn16[(size_t)bbv[i] * H_ + jpv[i]] = __float2half_rn(hnew);
      if (t == T_ - 1)
        out[(size_t)B_ * T_ * H_ + (size_t)bbv[i] * H_ + jv[i]] = hnew;
    }

    // ---- publish this CTA's h columns for step t+1 (release atomic
    //      replaces __threadfence + plain atomic: the ONLY delta vs R12) ----
    if (t < T_ - 1) {
      __syncthreads();
      if (tid == 0) red_release_add(&g_qcnt[myq], 1u);
    }
  }
}

// ============================================================================
extern "C" void kernel_launch(void* const* d_in, const int* in_sizes, int n_in,
                              void* d_out, int out_size) {
  const float* X   = (const float*)d_in[0];
  const float* Wih = (const float*)d_in[1];
  const float* Whh = (const float*)d_in[2];
  const float* bih = (const float*)d_in[3];
  const float* bhh = (const float*)d_in[4];
  const float* h0  = (const float*)d_in[5];
  float* out = (float*)d_out;

  cudaFuncSetAttribute(gi_gemm_kernel,
                       cudaFuncAttributeMaxDynamicSharedMemorySize,
                       P1_SMEM_BYTES);
  cudaFuncSetAttribute(gru_step_kernel,
                       cudaFuncAttributeMaxDynamicSharedMemorySize,
                       SMEM2_BYTES);

  // Phase 0: fp16-convert + k-permute X, W_ih, h0 (+ reset flag counters)
  prep_kernel<<<2048, 256>>>(X, Wih, h0);

  // Phase 1: input-side GEMM (fp16 m16n8k16, cp.async pipeline, 2 CTAs/SM)
  gi_gemm_kernel<<<dim3(24, 256), 128, P1_SMEM_BYTES>>>(bih);

  // Phase 2: persistent recurrence (128 CTAs, quarter flags, release publish)
  gru_step_kernel<<<GRID2, 128, SMEM2_BYTES>>>(Whh, bhh, h0, out);
}